// round 16
// baseline (speedup 1.0000x reference)
#include <cuda_runtime.h>
#include <cuda_fp16.h>
#include <cstdint>
#include <math.h>

// Problem constants
#define BB  2
#define TT  2048
#define CC  1024
#define HH  16
#define DD  64
#define N3  (3*CC)      // 3072
#define MM  (BB*TT)     // 4096

// Pre-converted operands (device globals: allocation-free)
__device__ __half g_xh[MM*CC];           // x in fp16 (hi only), [m][k]
__device__ __half g_wh[N3*CC];           // w in fp16 (hi only), K-major [n][k]
// Q,K,V fp16 (hi only) in [B,H,T,D]  (Q pre-scaled by 0.125*log2e)
__device__ __half g_qh[BB*HH*TT*DD];
__device__ __half g_kh[BB*HH*TT*DD];
__device__ __half g_vh[BB*HH*TT*DD];

// ===========================================================================
// Portable PTX helpers (sm_80+)
// ===========================================================================
__device__ __forceinline__ uint32_t smem_u32(const void* p) {
    uint32_t a;
    asm("{ .reg .u64 t; cvta.to.shared.u64 t, %1; cvt.u32.u64 %0, t; }"
        : "=r"(a) : "l"(p));
    return a;
}

__device__ __forceinline__ void ldsm_x4(uint32_t& r0, uint32_t& r1,
                                        uint32_t& r2, uint32_t& r3,
                                        uint32_t addr) {
    asm volatile("ldmatrix.sync.aligned.m8n8.x4.shared.b16 {%0,%1,%2,%3}, [%4];"
                 : "=r"(r0), "=r"(r1), "=r"(r2), "=r"(r3) : "r"(addr));
}

__device__ __forceinline__ void ldsm_x4_t(uint32_t& r0, uint32_t& r1,
                                          uint32_t& r2, uint32_t& r3,
                                          uint32_t addr) {
    asm volatile("ldmatrix.sync.aligned.m8n8.x4.trans.shared.b16 {%0,%1,%2,%3}, [%4];"
                 : "=r"(r0), "=r"(r1), "=r"(r2), "=r"(r3) : "r"(addr));
}

__device__ __forceinline__ void mma_f16(float* c,
                                        uint32_t a0, uint32_t a1,
                                        uint32_t a2, uint32_t a3,
                                        uint32_t b0, uint32_t b1) {
    asm volatile(
        "mma.sync.aligned.m16n8k16.row.col.f32.f16.f16.f32 "
        "{%0,%1,%2,%3}, {%4,%5,%6,%7}, {%8,%9}, {%0,%1,%2,%3};"
        : "+f"(c[0]), "+f"(c[1]), "+f"(c[2]), "+f"(c[3])
        : "r"(a0), "r"(a1), "r"(a2), "r"(a3), "r"(b0), "r"(b1));
}

// pack 2 fp32 -> rn-fp16x2
__device__ __forceinline__ uint32_t pack_h2(float v0, float v1) {
    uint32_t h;
    asm("cvt.rn.f16x2.f32 %0, %1, %2;" : "=r"(h) : "f"(v1), "f"(v0));
    return h;
}

// 2x exp2 in fp16 (one MUFU-class op for two elements)
__device__ __forceinline__ uint32_t ex2_h2(uint32_t d) {
    uint32_t r;
    asm("ex2.approx.f16x2 %0, %1;" : "=r"(r) : "r"(d));
    return r;
}

#define CP16(dst, src) \
    asm volatile("cp.async.cg.shared.global [%0], [%1], 16;" \
        :: "r"(dst), "l"(src) : "memory")
#define CP_COMMIT() asm volatile("cp.async.commit_group;" ::: "memory")
#define CP_WAIT(n)  asm volatile("cp.async.wait_group %0;" :: "n"(n) : "memory")

#define HONES 0x3C003C00u   // fp16 {1.0, 1.0}

// ===========================================================================
// Kernel 0a: x fp32 -> fp16 (hi only)
// ===========================================================================
__global__ __launch_bounds__(256)
void convert_x(const float* __restrict__ x)
{
    int i = (blockIdx.x * 256 + threadIdx.x) * 4;
    float4 v = *(const float4*)(x + i);
    uint2 o = make_uint2(pack_h2(v.x, v.y), pack_h2(v.z, v.w));
    *(uint2*)((char*)g_xh + (size_t)i * 2) = o;
}

// ===========================================================================
// Kernel 0b: w [k][n] fp32 -> wh fp16 (hi only), K-major [n][k]
// ===========================================================================
__global__ __launch_bounds__(128)
void convert_w(const float* __restrict__ w)
{
    int n  = blockIdx.x * 128 + threadIdx.x;
    int k0 = blockIdx.y * 16;
    const float* wp = w + (size_t)k0 * N3 + n;
    float v[16];
    #pragma unroll
    for (int q = 0; q < 16; ++q) v[q] = wp[(size_t)q * N3];
    uint32_t hi[8];
    #pragma unroll
    for (int q = 0; q < 8; ++q) hi[q] = pack_h2(v[2*q], v[2*q+1]);
    size_t off = ((size_t)n * CC + k0) * 2;
    *(uint4*)((char*)g_wh + off)      = make_uint4(hi[0], hi[1], hi[2], hi[3]);
    *(uint4*)((char*)g_wh + off + 16) = make_uint4(hi[4], hi[5], hi[6], hi[7]);
}

// ===========================================================================
// Kernel 1: QKV GEMM, fp16 1-term (Ah*Bh). CTA tile M=256 N=128 (512 thr),
// BK=64, cp.async triple buffer, one barrier per iteration. (unchanged)
// ===========================================================================
#define GP     144
#define GT128  (128*GP)        // 18432
#define GSTAGE (3*GT128)       // A(2) + Bh(1) = 55296
#define GEMM_SMEM (3*GSTAGE)   // 165888

__global__ __launch_bounds__(512, 1)
void qkv_gemm(const float* __restrict__ bias)
{
    extern __shared__ char smem[];
    const uint32_t sb = smem_u32(smem);

    const int tid = threadIdx.x;
    const int lid = tid & 31;
    const int wid = tid >> 5;          // 0..15
    const int wm  = wid & 7;           // 8 m-groups x 32 rows = 256
    const int wn  = wid >> 3;          // 2 n-groups x 64 cols
    const int n0  = blockIdx.x * 128;
    const int m0  = blockIdx.y * 256;

    const int a_r  = (lid & 7) + ((lid >> 3) & 1) * 8;
    const int a_cb = (lid >> 4) * 16;
    const int b_r  = ((lid >> 4) & 1) * 8 + (lid & 7);
    const int b_cb = ((lid >> 3) & 1) * 16;

    float acc[2][8][4];
    #pragma unroll
    for (int i = 0; i < 2; i++)
        #pragma unroll
        for (int j = 0; j < 8; j++)
            #pragma unroll
            for (int q = 0; q < 4; q++) acc[i][j][q] = 0.f;

    const int c_row = tid >> 3;        // 0..63
    const int c_c   = tid & 7;         // 16B chunk

    auto issue = [&](int it) {
        const int k0 = it * 64;
        const uint32_t s0 = sb + (it % 3) * GSTAGE;
        #pragma unroll
        for (int p = 0; p < 4; ++p) {
            int row = c_row + p * 64;  // 0..255
            CP16(s0 + row * GP + c_c * 16,
                 (const char*)g_xh + (((size_t)(m0 + row)) * CC + k0 + c_c * 8) * 2);
        }
        #pragma unroll
        for (int p = 0; p < 2; ++p) {
            int row = c_row + p * 64;  // 0..127
            size_t go = (((size_t)(n0 + row)) * CC + k0 + c_c * 8) * 2;
            CP16(s0 + 2 * GT128 + row * GP + c_c * 16, (const char*)g_wh + go);
        }
        CP_COMMIT();
    };

    auto compute = [&](int buf) {
        const uint32_t A  = sb + buf * GSTAGE;
        const uint32_t Bh = A + 2 * GT128;
        #pragma unroll
        for (int ks = 0; ks < 4; ++ks) {
            const int kb = ks * 32;
            uint32_t ah[2][4], bh[4][4];
            #pragma unroll
            for (int mt = 0; mt < 2; ++mt) {
                uint32_t ra = (wm * 32 + mt * 16 + a_r) * GP + a_cb + kb;
                ldsm_x4(ah[mt][0], ah[mt][1], ah[mt][2], ah[mt][3], A + ra);
            }
            #pragma unroll
            for (int bt = 0; bt < 4; ++bt) {
                uint32_t rb = (wn * 64 + bt * 16 + b_r) * GP + b_cb + kb;
                ldsm_x4(bh[bt][0], bh[bt][1], bh[bt][2], bh[bt][3], Bh + rb);
            }
            #pragma unroll
            for (int mt = 0; mt < 2; ++mt)
                #pragma unroll
                for (int nt = 0; nt < 8; ++nt)
                    mma_f16(acc[mt][nt], ah[mt][0], ah[mt][1], ah[mt][2], ah[mt][3],
                            bh[nt >> 1][(nt & 1) * 2], bh[nt >> 1][(nt & 1) * 2 + 1]);
        }
    };

    issue(0);
    issue(1);
    for (int it = 0; it < 16; ++it) {
        if (it < 15) { CP_WAIT(1); } else { CP_WAIT(0); }
        __syncthreads();
        if (it + 2 < 16) issue(it + 2);
        compute(it % 3);
    }

    // Epilogue: +bias, (Q: fold softmax scale), fp16 hi only, scatter
    {
        const int n_warp = n0 + wn * 64;
        const int which  = n_warp >> 10;
        const int ccn    = n_warp & (CC - 1);
        const int h      = ccn >> 6;
        __half* dh = (which == 0) ? g_qh : ((which == 1) ? g_kh : g_vh);
        const float qs = (which == 0) ? (0.125f * 1.44269504f) : 1.0f;

        #pragma unroll
        for (int mt = 0; mt < 2; ++mt) {
            int gm = m0 + wm * 32 + mt * 16 + (lid >> 2);
            #pragma unroll
            for (int half = 0; half < 2; ++half) {
                int gmr = gm + half * 8;
                int bb = gmr >> 11;
                int t  = gmr & (TT - 1);
                size_t rowhw = ((size_t)(bb * HH + h) * TT + t) * DD;
                #pragma unroll
                for (int nt = 0; nt < 8; ++nt) {
                    int d = nt * 8 + (lid & 3) * 2;
                    float2 bv = *(const float2*)(bias + n_warp + d);
                    float ox = (acc[mt][nt][half * 2 + 0] + bv.x) * qs;
                    float oy = (acc[mt][nt][half * 2 + 1] + bv.y) * qs;
                    *(uint32_t*)((char*)dh + (rowhw + d) * 2) = pack_h2(ox, oy);
                }
            }
        }
    }
}

// ===========================================================================
// Kernel 2: causal flash attention, fp16 hi, KV tile = 128. exp via
// ex2.approx.f16x2, FUSED into the PV loop per ks-chunk so scalar exp of
// chunk ks+1 issues while chunk ks's MMAs occupy the tensor pipe.
// ===========================================================================
#define AP 144
#define ATILE (128*AP)       // 18432 (128 kv rows)
#define ABUF  (2*ATILE)      // 36864: Kh, Vh
#define ATTN_SMEM (3*ABUF)   // 110592

__global__ __launch_bounds__(256, 1)
void attn_mma(float* __restrict__ out)
{
    extern __shared__ char smem[];
    const uint32_t sb = smem_u32(smem);

    const int tid = threadIdx.x;
    const int lid = tid & 31;
    const int wm  = tid >> 5;
    const int qi  = (int)(gridDim.x - 1 - blockIdx.x);   // big blocks first
    const int h   = blockIdx.y;
    const int b   = blockIdx.z;
    const int q0  = qi * 128;
    const size_t baseE = (size_t)(b * HH + h) * TT * DD;

    const int a_r  = (lid & 7) + ((lid >> 3) & 1) * 8;
    const int a_cb = (lid >> 4) * 16;
    const int b_r  = ((lid >> 4) & 1) * 8 + (lid & 7);
    const int b_cb = ((lid >> 3) & 1) * 16;

    // ---- Stage Q (fp16 hi, pre-scaled) via cp.async into buf region ----
    #pragma unroll
    for (int p = 0; p < 4; ++p) {
        int idx = p * 256 + tid;          // 0..1023
        int r   = idx >> 3;               // 0..127
        int c   = idx & 7;
        uint32_t dst = sb + r * AP + c * 16;
        const char* src = (const char*)g_qh +
            (baseE + (size_t)(q0 + r) * DD + c * 8) * 2;
        CP16(dst, src);
    }
    CP_COMMIT();
    CP_WAIT(0);
    __syncthreads();

    uint32_t qh[4][4];
    #pragma unroll
    for (int ks = 0; ks < 4; ++ks) {
        uint32_t ra = (wm * 16 + a_r) * AP + a_cb + ks * 32;
        ldsm_x4(qh[ks][0], qh[ks][1], qh[ks][2], qh[ks][3], sb + ra);
    }
    __syncthreads();

    float o[8][4];
    #pragma unroll
    for (int i = 0; i < 8; i++)
        #pragma unroll
        for (int j = 0; j < 4; j++) o[i][j] = 0.f;
    float lacc[4] = {0.f, 0.f, 0.f, 0.f};
    float m0 = -1e30f, m1 = -1e30f;

    const int row_min = q0 + wm * 16;
    const int r0g = row_min + (lid >> 2);
    const int col_e = (lid & 3) * 2;

    auto issue = [&](int j) {
        const uint32_t s0 = sb + (j % 3) * ABUF;
        #pragma unroll
        for (int p = 0; p < 8; ++p) {
            int idx = p * 256 + tid;      // 0..2047
            int sub = idx >> 10;          // 0 Kh, 1 Vh
            int r   = (idx >> 3) & 127;
            int c   = idx & 7;
            const __half* g = (sub == 0) ? g_kh : g_vh;
            uint32_t dst = s0 + sub * ATILE + r * AP + c * 16;
            const char* src = (const char*)g +
                (baseE + (size_t)(j * 128 + r) * DD + c * 8) * 2;
            CP16(dst, src);
        }
        CP_COMMIT();
    };

    const int ntiles = qi + 1;            // KV tiles of 128
    issue(0);
    if (ntiles > 1) issue(1);

    for (int j = 0; j < ntiles; ++j) {
        if (j + 1 < ntiles) { CP_WAIT(1); } else { CP_WAIT(0); }
        __syncthreads();
        if (j + 2 < ntiles) issue(j + 2);

        const uint32_t bufb = sb + (j % 3) * ABUF;

        // ---- S = Qh Kh^T (1-term fp16), 16x128 per warp ----
        float s[16][4];
        #pragma unroll
        for (int i = 0; i < 16; i++)
            #pragma unroll
            for (int q = 0; q < 4; q++) s[i][q] = 0.f;

        #pragma unroll
        for (int ks = 0; ks < 4; ++ks) {
            uint32_t bh[8][4];
            #pragma unroll
            for (int ng = 0; ng < 8; ++ng) {
                uint32_t rb = (ng * 16 + b_r) * AP + b_cb + ks * 32;
                ldsm_x4(bh[ng][0], bh[ng][1], bh[ng][2], bh[ng][3], bufb + rb);
            }
            #pragma unroll
            for (int nt = 0; nt < 16; ++nt)
                mma_f16(s[nt], qh[ks][0], qh[ks][1], qh[ks][2], qh[ks][3],
                        bh[nt >> 1][(nt & 1) * 2], bh[nt >> 1][(nt & 1) * 2 + 1]);
        }

        // ---- causal mask (S already scaled via Q) ----
        if (j * 128 + 127 > row_min) {
            #pragma unroll
            for (int nt = 0; nt < 16; ++nt) {
                int c0 = j * 128 + nt * 8 + col_e;
                if (c0     > r0g)     s[nt][0] = -1e30f;
                if (c0 + 1 > r0g)     s[nt][1] = -1e30f;
                if (c0     > r0g + 8) s[nt][2] = -1e30f;
                if (c0 + 1 > r0g + 8) s[nt][3] = -1e30f;
            }
        }

        // ---- online softmax max (base-2 domain) ----
        float mx0 = -1e30f, mx1 = -1e30f;
        #pragma unroll
        for (int nt = 0; nt < 16; ++nt) {
            mx0 = fmaxf(mx0, fmaxf(s[nt][0], s[nt][1]));
            mx1 = fmaxf(mx1, fmaxf(s[nt][2], s[nt][3]));
        }
        mx0 = fmaxf(mx0, __shfl_xor_sync(0xffffffffu, mx0, 1));
        mx0 = fmaxf(mx0, __shfl_xor_sync(0xffffffffu, mx0, 2));
        mx1 = fmaxf(mx1, __shfl_xor_sync(0xffffffffu, mx1, 1));
        mx1 = fmaxf(mx1, __shfl_xor_sync(0xffffffffu, mx1, 2));
        float m0n = fmaxf(m0, mx0), m1n = fmaxf(m1, mx1);
        float f0 = exp2f(m0 - m0n), f1 = exp2f(m1 - m1n);
        m0 = m0n; m1 = m1n;

        // rescale running accumulators (once per 128 kv)
        #pragma unroll
        for (int nt = 0; nt < 8; ++nt) {
            o[nt][0] *= f0; o[nt][1] *= f0;
            o[nt][2] *= f1; o[nt][3] *= f1;
        }
        lacc[0] *= f0; lacc[1] *= f0; lacc[2] *= f1; lacc[3] *= f1;

        // ---- FUSED exp + PV per ks-chunk: scalar exp of chunk ks+1 issues
        //      while chunk ks's MMAs occupy the tensor pipe ----
        #pragma unroll
        for (int ks = 0; ks < 8; ++ks) {
            uint32_t pa[4];
            pa[0] = ex2_h2(pack_h2(s[2*ks    ][0] - m0n, s[2*ks    ][1] - m0n));
            pa[1] = ex2_h2(pack_h2(s[2*ks    ][2] - m1n, s[2*ks    ][3] - m1n));
            pa[2] = ex2_h2(pack_h2(s[2*ks + 1][0] - m0n, s[2*ks + 1][1] - m0n));
            pa[3] = ex2_h2(pack_h2(s[2*ks + 1][2] - m1n, s[2*ks + 1][3] - m1n));
            mma_f16(lacc, pa[0], pa[1], pa[2], pa[3], HONES, HONES);
            #pragma unroll
            for (int dg = 0; dg < 4; ++dg) {
                uint32_t vh[4];
                uint32_t rv = (ks * 16 + a_r) * AP + dg * 32 + a_cb;
                ldsm_x4_t(vh[0], vh[1], vh[2], vh[3], bufb + ATILE + rv);
                int nt = dg * 2;
                mma_f16(o[nt],     pa[0], pa[1], pa[2], pa[3], vh[0], vh[1]);
                mma_f16(o[nt + 1], pa[0], pa[1], pa[2], pa[3], vh[2], vh[3]);
            }
        }
        __syncthreads();
    }

    // ---- finalize: divide by l, write [B,T,C] fp32 ----
    {
        float inv0 = 1.0f / lacc[0], inv1 = 1.0f / lacc[2];
        #pragma unroll
        for (int nt = 0; nt < 8; ++nt) {
            int c = h * 64 + nt * 8 + col_e;
            float2 v0 = make_float2(o[nt][0] * inv0, o[nt][1] * inv0);
            float2 v1 = make_float2(o[nt][2] * inv1, o[nt][3] * inv1);
            *(float2*)(out + (size_t)(b * TT + r0g)     * CC + c) = v0;
            *(float2*)(out + (size_t)(b * TT + r0g + 8) * CC + c) = v1;
        }
    }
}

// ---------------------------------------------------------------------------
extern "C" void kernel_launch(void* const* d_in, const int* in_sizes, int n_in,
                              void* d_out, int out_size)
{
    const float* x    = (const float*)d_in[0];   // [2,2048,1024]
    const float* w    = (const float*)d_in[1];   // [1024,3072]
    const float* bias = (const float*)d_in[2];   // [3072]
    float* out = (float*)d_out;                  // [2,2048,1024]

    cudaFuncSetAttribute((const void*)qkv_gemm,
                         cudaFuncAttributeMaxDynamicSharedMemorySize, GEMM_SMEM);
    cudaFuncSetAttribute((const void*)attn_mma,
                         cudaFuncAttributeMaxDynamicSharedMemorySize, ATTN_SMEM);

    convert_x<<<MM * CC / 1024, 256>>>(x);
    convert_w<<<dim3(N3 / 128, CC / 16), 128>>>(w);
    qkv_gemm<<<dim3(N3 / 128, MM / 256), 512, GEMM_SMEM>>>(bias);
    attn_mma<<<dim3(TT / 128, HH, BB), 256, ATTN_SMEM>>>(out);
}

// round 17
// speedup vs baseline: 1.0135x; 1.0135x over previous
#include <cuda_runtime.h>
#include <cuda_fp16.h>
#include <cstdint>
#include <math.h>

// Problem constants
#define BB  2
#define TT  2048
#define CC  1024
#define HH  16
#define DD  64
#define N3  (3*CC)      // 3072
#define MM  (BB*TT)     // 4096

// Pre-converted operands (device globals: allocation-free)
__device__ __half g_xh[MM*CC];           // x in fp16 (hi only), [m][k]
__device__ __half g_wh[N3*CC];           // w in fp16 (hi only), K-major [n][k]
// Q,K,V fp16 (hi only) in [B,H,T,D]  (Q pre-scaled by 0.125*log2e)
__device__ __half g_qh[BB*HH*TT*DD];
__device__ __half g_kh[BB*HH*TT*DD];
__device__ __half g_vh[BB*HH*TT*DD];

// ===========================================================================
// Portable PTX helpers (sm_80+)
// ===========================================================================
__device__ __forceinline__ uint32_t smem_u32(const void* p) {
    uint32_t a;
    asm("{ .reg .u64 t; cvta.to.shared.u64 t, %1; cvt.u32.u64 %0, t; }"
        : "=r"(a) : "l"(p));
    return a;
}

__device__ __forceinline__ void ldsm_x4(uint32_t& r0, uint32_t& r1,
                                        uint32_t& r2, uint32_t& r3,
                                        uint32_t addr) {
    asm volatile("ldmatrix.sync.aligned.m8n8.x4.shared.b16 {%0,%1,%2,%3}, [%4];"
                 : "=r"(r0), "=r"(r1), "=r"(r2), "=r"(r3) : "r"(addr));
}

__device__ __forceinline__ void ldsm_x4_t(uint32_t& r0, uint32_t& r1,
                                          uint32_t& r2, uint32_t& r3,
                                          uint32_t addr) {
    asm volatile("ldmatrix.sync.aligned.m8n8.x4.trans.shared.b16 {%0,%1,%2,%3}, [%4];"
                 : "=r"(r0), "=r"(r1), "=r"(r2), "=r"(r3) : "r"(addr));
}

__device__ __forceinline__ void mma_f16(float* c,
                                        uint32_t a0, uint32_t a1,
                                        uint32_t a2, uint32_t a3,
                                        uint32_t b0, uint32_t b1) {
    asm volatile(
        "mma.sync.aligned.m16n8k16.row.col.f32.f16.f16.f32 "
        "{%0,%1,%2,%3}, {%4,%5,%6,%7}, {%8,%9}, {%0,%1,%2,%3};"
        : "+f"(c[0]), "+f"(c[1]), "+f"(c[2]), "+f"(c[3])
        : "r"(a0), "r"(a1), "r"(a2), "r"(a3), "r"(b0), "r"(b1));
}

// pack 2 fp32 -> rn-fp16x2
__device__ __forceinline__ uint32_t pack_h2(float v0, float v1) {
    uint32_t h;
    asm("cvt.rn.f16x2.f32 %0, %1, %2;" : "=r"(h) : "f"(v1), "f"(v0));
    return h;
}

// 2x exp2 in fp16 (one MUFU-class op for two elements)
__device__ __forceinline__ uint32_t ex2_h2(uint32_t d) {
    uint32_t r;
    asm("ex2.approx.f16x2 %0, %1;" : "=r"(r) : "r"(d));
    return r;
}

#define CP16(dst, src) \
    asm volatile("cp.async.cg.shared.global [%0], [%1], 16;" \
        :: "r"(dst), "l"(src) : "memory")
#define CP_COMMIT() asm volatile("cp.async.commit_group;" ::: "memory")
#define CP_WAIT(n)  asm volatile("cp.async.wait_group %0;" :: "n"(n) : "memory")

#define HONES 0x3C003C00u   // fp16 {1.0, 1.0}

template <bool V> struct BoolC { static constexpr bool value = V; };

// ===========================================================================
// Kernel 0a: x fp32 -> fp16 (hi only)
// ===========================================================================
__global__ __launch_bounds__(256)
void convert_x(const float* __restrict__ x)
{
    int i = (blockIdx.x * 256 + threadIdx.x) * 4;
    float4 v = *(const float4*)(x + i);
    uint2 o = make_uint2(pack_h2(v.x, v.y), pack_h2(v.z, v.w));
    *(uint2*)((char*)g_xh + (size_t)i * 2) = o;
}

// ===========================================================================
// Kernel 0b: w [k][n] fp32 -> wh fp16 (hi only), K-major [n][k]
// ===========================================================================
__global__ __launch_bounds__(128)
void convert_w(const float* __restrict__ w)
{
    int n  = blockIdx.x * 128 + threadIdx.x;
    int k0 = blockIdx.y * 16;
    const float* wp = w + (size_t)k0 * N3 + n;
    float v[16];
    #pragma unroll
    for (int q = 0; q < 16; ++q) v[q] = wp[(size_t)q * N3];
    uint32_t hi[8];
    #pragma unroll
    for (int q = 0; q < 8; ++q) hi[q] = pack_h2(v[2*q], v[2*q+1]);
    size_t off = ((size_t)n * CC + k0) * 2;
    *(uint4*)((char*)g_wh + off)      = make_uint4(hi[0], hi[1], hi[2], hi[3]);
    *(uint4*)((char*)g_wh + off + 16) = make_uint4(hi[4], hi[5], hi[6], hi[7]);
}

// ===========================================================================
// Kernel 1: QKV GEMM, fp16 1-term (Ah*Bh). CTA tile M=256 N=128 (512 thr),
// BK=64, cp.async triple buffer, one barrier per iteration. (unchanged)
// ===========================================================================
#define GP     144
#define GT128  (128*GP)        // 18432
#define GSTAGE (3*GT128)       // A(2) + Bh(1) = 55296
#define GEMM_SMEM (3*GSTAGE)   // 165888

__global__ __launch_bounds__(512, 1)
void qkv_gemm(const float* __restrict__ bias)
{
    extern __shared__ char smem[];
    const uint32_t sb = smem_u32(smem);

    const int tid = threadIdx.x;
    const int lid = tid & 31;
    const int wid = tid >> 5;          // 0..15
    const int wm  = wid & 7;           // 8 m-groups x 32 rows = 256
    const int wn  = wid >> 3;          // 2 n-groups x 64 cols
    const int n0  = blockIdx.x * 128;
    const int m0  = blockIdx.y * 256;

    const int a_r  = (lid & 7) + ((lid >> 3) & 1) * 8;
    const int a_cb = (lid >> 4) * 16;
    const int b_r  = ((lid >> 4) & 1) * 8 + (lid & 7);
    const int b_cb = ((lid >> 3) & 1) * 16;

    float acc[2][8][4];
    #pragma unroll
    for (int i = 0; i < 2; i++)
        #pragma unroll
        for (int j = 0; j < 8; j++)
            #pragma unroll
            for (int q = 0; q < 4; q++) acc[i][j][q] = 0.f;

    const int c_row = tid >> 3;        // 0..63
    const int c_c   = tid & 7;         // 16B chunk

    auto issue = [&](int it) {
        const int k0 = it * 64;
        const uint32_t s0 = sb + (it % 3) * GSTAGE;
        #pragma unroll
        for (int p = 0; p < 4; ++p) {
            int row = c_row + p * 64;  // 0..255
            CP16(s0 + row * GP + c_c * 16,
                 (const char*)g_xh + (((size_t)(m0 + row)) * CC + k0 + c_c * 8) * 2);
        }
        #pragma unroll
        for (int p = 0; p < 2; ++p) {
            int row = c_row + p * 64;  // 0..127
            size_t go = (((size_t)(n0 + row)) * CC + k0 + c_c * 8) * 2;
            CP16(s0 + 2 * GT128 + row * GP + c_c * 16, (const char*)g_wh + go);
        }
        CP_COMMIT();
    };

    auto compute = [&](int buf) {
        const uint32_t A  = sb + buf * GSTAGE;
        const uint32_t Bh = A + 2 * GT128;
        #pragma unroll
        for (int ks = 0; ks < 4; ++ks) {
            const int kb = ks * 32;
            uint32_t ah[2][4], bh[4][4];
            #pragma unroll
            for (int mt = 0; mt < 2; ++mt) {
                uint32_t ra = (wm * 32 + mt * 16 + a_r) * GP + a_cb + kb;
                ldsm_x4(ah[mt][0], ah[mt][1], ah[mt][2], ah[mt][3], A + ra);
            }
            #pragma unroll
            for (int bt = 0; bt < 4; ++bt) {
                uint32_t rb = (wn * 64 + bt * 16 + b_r) * GP + b_cb + kb;
                ldsm_x4(bh[bt][0], bh[bt][1], bh[bt][2], bh[bt][3], Bh + rb);
            }
            #pragma unroll
            for (int mt = 0; mt < 2; ++mt)
                #pragma unroll
                for (int nt = 0; nt < 8; ++nt)
                    mma_f16(acc[mt][nt], ah[mt][0], ah[mt][1], ah[mt][2], ah[mt][3],
                            bh[nt >> 1][(nt & 1) * 2], bh[nt >> 1][(nt & 1) * 2 + 1]);
        }
    };

    issue(0);
    issue(1);
    for (int it = 0; it < 16; ++it) {
        if (it < 15) { CP_WAIT(1); } else { CP_WAIT(0); }
        __syncthreads();
        if (it + 2 < 16) issue(it + 2);
        compute(it % 3);
    }

    // Epilogue: +bias, (Q: fold softmax scale), fp16 hi only, scatter
    {
        const int n_warp = n0 + wn * 64;
        const int which  = n_warp >> 10;
        const int ccn    = n_warp & (CC - 1);
        const int h      = ccn >> 6;
        __half* dh = (which == 0) ? g_qh : ((which == 1) ? g_kh : g_vh);
        const float qs = (which == 0) ? (0.125f * 1.44269504f) : 1.0f;

        #pragma unroll
        for (int mt = 0; mt < 2; ++mt) {
            int gm = m0 + wm * 32 + mt * 16 + (lid >> 2);
            #pragma unroll
            for (int half = 0; half < 2; ++half) {
                int gmr = gm + half * 8;
                int bb = gmr >> 11;
                int t  = gmr & (TT - 1);
                size_t rowhw = ((size_t)(bb * HH + h) * TT + t) * DD;
                #pragma unroll
                for (int nt = 0; nt < 8; ++nt) {
                    int d = nt * 8 + (lid & 3) * 2;
                    float2 bv = *(const float2*)(bias + n_warp + d);
                    float ox = (acc[mt][nt][half * 2 + 0] + bv.x) * qs;
                    float oy = (acc[mt][nt][half * 2 + 1] + bv.y) * qs;
                    *(uint32_t*)((char*)dh + (rowhw + d) * 2) = pack_h2(ox, oy);
                }
            }
        }
    }
}

// ===========================================================================
// Kernel 2: causal flash attention, fp16 hi, KV tile = 128, exp via
// ex2.approx.f16x2. Diagonal tile specialization: warp wm only computes
// S chunks ng<=wm and PV chunks ks<=wm (rest exactly masked -> P=0).
// ===========================================================================
#define AP 144
#define ATILE (128*AP)       // 18432 (128 kv rows)
#define ABUF  (2*ATILE)      // 36864: Kh, Vh
#define ATTN_SMEM (3*ABUF)   // 110592

__global__ __launch_bounds__(256, 1)
void attn_mma(float* __restrict__ out)
{
    extern __shared__ char smem[];
    const uint32_t sb = smem_u32(smem);

    const int tid = threadIdx.x;
    const int lid = tid & 31;
    const int wm  = tid >> 5;
    const int qi  = (int)(gridDim.x - 1 - blockIdx.x);   // big blocks first
    const int h   = blockIdx.y;
    const int b   = blockIdx.z;
    const int q0  = qi * 128;
    const size_t baseE = (size_t)(b * HH + h) * TT * DD;

    const int a_r  = (lid & 7) + ((lid >> 3) & 1) * 8;
    const int a_cb = (lid >> 4) * 16;
    const int b_r  = ((lid >> 4) & 1) * 8 + (lid & 7);
    const int b_cb = ((lid >> 3) & 1) * 16;

    // ---- Stage Q (fp16 hi, pre-scaled) via cp.async into buf region ----
    #pragma unroll
    for (int p = 0; p < 4; ++p) {
        int idx = p * 256 + tid;          // 0..1023
        int r   = idx >> 3;               // 0..127
        int c   = idx & 7;
        uint32_t dst = sb + r * AP + c * 16;
        const char* src = (const char*)g_qh +
            (baseE + (size_t)(q0 + r) * DD + c * 8) * 2;
        CP16(dst, src);
    }
    CP_COMMIT();
    CP_WAIT(0);
    __syncthreads();

    uint32_t qh[4][4];
    #pragma unroll
    for (int ks = 0; ks < 4; ++ks) {
        uint32_t ra = (wm * 16 + a_r) * AP + a_cb + ks * 32;
        ldsm_x4(qh[ks][0], qh[ks][1], qh[ks][2], qh[ks][3], sb + ra);
    }
    __syncthreads();

    float o[8][4];
    #pragma unroll
    for (int i = 0; i < 8; i++)
        #pragma unroll
        for (int j = 0; j < 4; j++) o[i][j] = 0.f;
    float lacc[4] = {0.f, 0.f, 0.f, 0.f};
    float m0 = -1e30f, m1 = -1e30f;

    const int row_min = q0 + wm * 16;
    const int r0g = row_min + (lid >> 2);
    const int col_e = (lid & 3) * 2;

    auto issue = [&](int j) {
        const uint32_t s0 = sb + (j % 3) * ABUF;
        #pragma unroll
        for (int p = 0; p < 8; ++p) {
            int idx = p * 256 + tid;      // 0..2047
            int sub = idx >> 10;          // 0 Kh, 1 Vh
            int r   = (idx >> 3) & 127;
            int c   = idx & 7;
            const __half* g = (sub == 0) ? g_kh : g_vh;
            uint32_t dst = s0 + sub * ATILE + r * AP + c * 16;
            const char* src = (const char*)g +
                (baseE + (size_t)(j * 128 + r) * DD + c * 8) * 2;
            CP16(dst, src);
        }
        CP_COMMIT();
    };

    const int ntiles = qi + 1;            // KV tiles of 128
    issue(0);
    if (ntiles > 1) issue(1);

    // ---- tile body, specialized on DIAG (diagonal tile: chunk skipping) ----
    auto body = [&](int j, auto DIAGC) {
        constexpr bool DIAG = decltype(DIAGC)::value;
        const uint32_t bufb = sb + (j % 3) * ABUF;

        // ---- S = Qh Kh^T (1-term fp16), 16x128 per warp ----
        float s[16][4];
        #pragma unroll
        for (int i = 0; i < 16; i++)
            #pragma unroll
            for (int q = 0; q < 4; q++) s[i][q] = 0.f;

        #pragma unroll
        for (int ks = 0; ks < 4; ++ks) {
            uint32_t bh[8][4];
            #pragma unroll
            for (int ng = 0; ng < 8; ++ng) {
                if (DIAG && ng > wm) continue;     // fully-masked chunk
                uint32_t rb = (ng * 16 + b_r) * AP + b_cb + ks * 32;
                ldsm_x4(bh[ng][0], bh[ng][1], bh[ng][2], bh[ng][3], bufb + rb);
            }
            #pragma unroll
            for (int nt = 0; nt < 16; ++nt) {
                if (DIAG && (nt >> 1) > wm) continue;
                mma_f16(s[nt], qh[ks][0], qh[ks][1], qh[ks][2], qh[ks][3],
                        bh[nt >> 1][(nt & 1) * 2], bh[nt >> 1][(nt & 1) * 2 + 1]);
            }
        }

        // ---- causal mask (diag only; partial chunks handled elementwise) ----
        if (DIAG) {
            #pragma unroll
            for (int nt = 0; nt < 16; ++nt) {
                if ((nt >> 1) > wm) continue;
                int c0 = j * 128 + nt * 8 + col_e;
                if (c0     > r0g)     s[nt][0] = -1e30f;
                if (c0 + 1 > r0g)     s[nt][1] = -1e30f;
                if (c0     > r0g + 8) s[nt][2] = -1e30f;
                if (c0 + 1 > r0g + 8) s[nt][3] = -1e30f;
            }
        }

        // ---- online softmax max (base-2 domain) ----
        float mx0 = -1e30f, mx1 = -1e30f;
        #pragma unroll
        for (int nt = 0; nt < 16; ++nt) {
            if (DIAG && (nt >> 1) > wm) continue;
            mx0 = fmaxf(mx0, fmaxf(s[nt][0], s[nt][1]));
            mx1 = fmaxf(mx1, fmaxf(s[nt][2], s[nt][3]));
        }
        mx0 = fmaxf(mx0, __shfl_xor_sync(0xffffffffu, mx0, 1));
        mx0 = fmaxf(mx0, __shfl_xor_sync(0xffffffffu, mx0, 2));
        mx1 = fmaxf(mx1, __shfl_xor_sync(0xffffffffu, mx1, 1));
        mx1 = fmaxf(mx1, __shfl_xor_sync(0xffffffffu, mx1, 2));
        float m0n = fmaxf(m0, mx0), m1n = fmaxf(m1, mx1);
        float f0 = exp2f(m0 - m0n), f1 = exp2f(m1 - m1n);
        m0 = m0n; m1 = m1n;

        // rescale running accumulators (once per 128 kv)
        #pragma unroll
        for (int nt = 0; nt < 8; ++nt) {
            o[nt][0] *= f0; o[nt][1] *= f0;
            o[nt][2] *= f1; o[nt][3] *= f1;
        }
        lacc[0] *= f0; lacc[1] *= f0; lacc[2] *= f1; lacc[3] *= f1;

        // ---- exp (ex2.approx.f16x2) fused with PV per ks-chunk ----
        #pragma unroll
        for (int ks = 0; ks < 8; ++ks) {
            if (DIAG && ks > wm) continue;         // P == 0 for these rows
            uint32_t pa[4];
            pa[0] = ex2_h2(pack_h2(s[2*ks    ][0] - m0n, s[2*ks    ][1] - m0n));
            pa[1] = ex2_h2(pack_h2(s[2*ks    ][2] - m1n, s[2*ks    ][3] - m1n));
            pa[2] = ex2_h2(pack_h2(s[2*ks + 1][0] - m0n, s[2*ks + 1][1] - m0n));
            pa[3] = ex2_h2(pack_h2(s[2*ks + 1][2] - m1n, s[2*ks + 1][3] - m1n));
            mma_f16(lacc, pa[0], pa[1], pa[2], pa[3], HONES, HONES);
            #pragma unroll
            for (int dg = 0; dg < 4; ++dg) {
                uint32_t vh[4];
                uint32_t rv = (ks * 16 + a_r) * AP + dg * 32 + a_cb;
                ldsm_x4_t(vh[0], vh[1], vh[2], vh[3], bufb + ATILE + rv);
                int nt = dg * 2;
                mma_f16(o[nt],     pa[0], pa[1], pa[2], pa[3], vh[0], vh[1]);
                mma_f16(o[nt + 1], pa[0], pa[1], pa[2], pa[3], vh[2], vh[3]);
            }
        }
    };

    for (int j = 0; j < ntiles; ++j) {
        if (j + 1 < ntiles) { CP_WAIT(1); } else { CP_WAIT(0); }
        __syncthreads();
        if (j + 2 < ntiles) issue(j + 2);

        if (j == ntiles - 1) body(j, BoolC<true>());
        else                 body(j, BoolC<false>());

        __syncthreads();
    }

    // ---- finalize: divide by l, write [B,T,C] fp32 ----
    {
        float inv0 = 1.0f / lacc[0], inv1 = 1.0f / lacc[2];
        #pragma unroll
        for (int nt = 0; nt < 8; ++nt) {
            int c = h * 64 + nt * 8 + col_e;
            float2 v0 = make_float2(o[nt][0] * inv0, o[nt][1] * inv0);
            float2 v1 = make_float2(o[nt][2] * inv1, o[nt][3] * inv1);
            *(float2*)(out + (size_t)(b * TT + r0g)     * CC + c) = v0;
            *(float2*)(out + (size_t)(b * TT + r0g + 8) * CC + c) = v1;
        }
    }
}

// ---------------------------------------------------------------------------
extern "C" void kernel_launch(void* const* d_in, const int* in_sizes, int n_in,
                              void* d_out, int out_size)
{
    const float* x    = (const float*)d_in[0];   // [2,2048,1024]
    const float* w    = (const float*)d_in[1];   // [1024,3072]
    const float* bias = (const float*)d_in[2];   // [3072]
    float* out = (float*)d_out;                  // [2,2048,1024]

    cudaFuncSetAttribute((const void*)qkv_gemm,
                         cudaFuncAttributeMaxDynamicSharedMemorySize, GEMM_SMEM);
    cudaFuncSetAttribute((const void*)attn_mma,
                         cudaFuncAttributeMaxDynamicSharedMemorySize, ATTN_SMEM);

    convert_x<<<MM * CC / 1024, 256>>>(x);
    convert_w<<<dim3(N3 / 128, CC / 16), 128>>>(w);
    qkv_gemm<<<dim3(N3 / 128, MM / 256), 512, GEMM_SMEM>>>(bias);
    attn_mma<<<dim3(TT / 128, HH, BB), 256, ATTN_SMEM>>>(out);
}